// round 15
// baseline (speedup 1.0000x reference)
#include <cuda_runtime.h>
#include <cuda_bf16.h>
#include <math.h>

#define T_STEPS 400
#define BATCH 128
#define HID 512
#define OC 64
#define NSPLIT 8
#define K1P 640
#define K1S 80
#define G1 5
#define K2 1024
#define K2S 128
#define G2 8
#define W1PITCH 88
#define W2PITCH 136
#define SM_W1 0
#define SM_W2 67584
#define SM_B  172032
#define SMEM_TOTAL 227328
#define BPLANE 6144
#define BBUF 18432

typedef unsigned long long ull;
typedef unsigned short u16;
typedef unsigned int u32;

__device__ __align__(16) float g_ybuf[OC * T_STEPS * BATCH];
__device__ __align__(16) float g_seq [T_STEPS * OC * BATCH];
__device__ float g_scale[OC];
__device__ float g_shift[OC];
__device__ __align__(16) float g_memL[OC * BATCH];
__device__ __align__(16) float g_mem1f[HID * BATCH];
__device__ __align__(16) float g_mem2f[HID * BATCH];
__device__ __align__(16) float g_syn1[HID * BATCH];
__device__ __align__(16) float g_syn2[HID * BATCH];
__device__ __align__(16) float g_acc2[HID * BATCH];
__device__ __align__(16) float g_partA[NSPLIT * 2048 * BATCH];
__device__ __align__(16) float g_partB[NSPLIT * 2048 * BATCH];
__device__ __align__(16) u16 g_St1[3][BATCH * K1P];
__device__ __align__(16) u16 g_St2[3][BATCH * K2];
__device__ unsigned g_flags[128];
__device__ unsigned g_phase;

__device__ __forceinline__ float sigf(float x) { return 1.f / (1.f + expf(-x)); }
__device__ __forceinline__ u32 smem_u32(const void* p) {
    u32 a; asm("{ .reg .u64 t; cvta.to.shared.u64 t, %1; cvt.u32.u64 %0, t; }" : "=r"(a) : "l"(p));
    return a;
}
__device__ __forceinline__ void cpa16s(u32 dst, const void* src) {
    asm volatile("cp.async.cg.shared.global [%0], [%1], 16;" :: "r"(dst), "l"(src));
}
#define CP_COMMIT() asm volatile("cp.async.commit_group;" ::: "memory")
__device__ __forceinline__ void split3(float x, u16& h, u16& m, u16& l) {
    __nv_bfloat16 bh = __float2bfloat16(x);
    float r = x - __bfloat162float(bh);
    __nv_bfloat16 bm = __float2bfloat16(r);
    __nv_bfloat16 bl = __float2bfloat16(r - __bfloat162float(bm));
    h = *(u16*)&bh; m = *(u16*)&bm; l = *(u16*)&bl;
}
__device__ __forceinline__ void ldsm_x4(u32& r0, u32& r1, u32& r2, u32& r3, u32 addr) {
    asm volatile("ldmatrix.sync.aligned.m8n8.x4.shared.b16 {%0,%1,%2,%3}, [%4];"
        : "=r"(r0), "=r"(r1), "=r"(r2), "=r"(r3) : "r"(addr));
}
__device__ __forceinline__ void mma16816(float* c, const u32* a, const u32* b) {
    asm volatile("mma.sync.aligned.m16n8k16.row.col.f32.bf16.bf16.f32 "
        "{%0,%1,%2,%3},{%4,%5,%6,%7},{%8,%9},{%0,%1,%2,%3};"
        : "+f"(c[0]), "+f"(c[1]), "+f"(c[2]), "+f"(c[3])
        : "r"(a[0]), "r"(a[1]), "r"(a[2]), "r"(a[3]), "r"(b[0]), "r"(b[1]));
}

__device__ __forceinline__ void grid_barrier(unsigned ph) {
    __syncthreads();
    if (threadIdx.x == 0)
        asm volatile("st.release.gpu.u32 [%0], %1;" :: "l"(g_flags + blockIdx.x), "r"(ph) : "memory");
    if (blockIdx.x == 0) {
        if (threadIdx.x < 128) {
            unsigned v;
            do { asm volatile("ld.acquire.gpu.u32 %0, [%1];" : "=r"(v) : "l"(g_flags + threadIdx.x)); }
            while ((int)(v - ph) < 0);
        }
        __syncthreads();
        if (threadIdx.x == 0)
            asm volatile("st.release.gpu.u32 [%0], %1;" :: "l"(&g_phase), "r"(ph) : "memory");
    } else if (threadIdx.x == 0) {
        unsigned v;
        do { asm volatile("ld.acquire.gpu.u32 %0, [%1];" : "=r"(v) : "l"(&g_phase)); }
        while ((int)(v - ph) < 0);
    }
    __syncthreads();
}

__global__ void conv_kernel(const float* __restrict__ x, const float* __restrict__ w) {
    __shared__ float s_w[OC * 70];
    int t = blockIdx.x, b = threadIdx.x;
    for (int i = b; i < OC * 70; i += 128) s_w[i] = w[i];
    float xr[5][14];
#pragma unroll
    for (int k = 0; k < 5; k++) {
        int tt = t + k - 2;
        bool ok = (tt >= 0 && tt < T_STEPS);
#pragma unroll
        for (int c = 0; c < 14; c++) xr[k][c] = ok ? x[(tt * BATCH + b) * 14 + c] : 0.f;
    }
    __syncthreads();
    for (int oc = 0; oc < OC; oc++) {
        float acc = 0.f;
        const float* wr = s_w + oc * 70;
#pragma unroll
        for (int c = 0; c < 14; c++)
#pragma unroll
            for (int k = 0; k < 5; k++) acc = fmaf(xr[k][c], wr[c * 5 + k], acc);
        g_ybuf[oc * (T_STEPS * BATCH) + t * BATCH + b] = acc;
    }
}

__global__ void stats_kernel(const float* __restrict__ bn_g, const float* __restrict__ bn_b) {
    int c = blockIdx.x;
    const float* base = g_ybuf + c * (T_STEPS * BATCH);
    double s = 0.0, sq = 0.0;
    for (int i = threadIdx.x; i < T_STEPS * BATCH; i += 256) {
        float v = base[i]; s += v; sq += (double)v * (double)v;
    }
    __shared__ double rs[256], rq[256];
    rs[threadIdx.x] = s; rq[threadIdx.x] = sq;
    __syncthreads();
    for (int st = 128; st > 0; st >>= 1) {
        if (threadIdx.x < st) { rs[threadIdx.x] += rs[threadIdx.x + st]; rq[threadIdx.x] += rq[threadIdx.x + st]; }
        __syncthreads();
    }
    if (threadIdx.x == 0) {
        double n = (double)(T_STEPS * BATCH);
        double mu = rs[0] / n, var = rq[0] / n - mu * mu;
        float sc = bn_g[c] * (float)(1.0 / sqrt(var + 1e-5));
        g_scale[c] = sc; g_shift[c] = bn_b[c] - (float)mu * sc;
    }
}

__global__ void norm_kernel() {
    int i = blockIdx.x * 256 + threadIdx.x;
    if (i >= OC * T_STEPS * BATCH) return;
    int oc = i / (T_STEPS * BATCH), rem = i % (T_STEPS * BATCH);
    g_seq[(rem / BATCH) * (OC * BATCH) + oc * BATCH + (rem % BATCH)] = g_ybuf[i] * g_scale[oc] + g_shift[oc];
}

// gemm: NG 16-k groups; 32 warps, warp tile m32 x n16 (4 x 8 warp grid)
template <int NG, int KG>
__device__ __forceinline__ void gemm_mma(const u16* stbase, int kofs, u32 wsm, int wpitchB,
                                         u32 bsm, float* __restrict__ spart, int warp, int lane) {
    auto fetch = [&](int g) {
        if (g < NG) {
            int buf = g % 3;
            for (int i = threadIdx.x; i < 768; i += 1024) {
                int v = i >> 8, rem = i & 255, b = rem >> 1, hf = rem & 1;
                cpa16s(bsm + buf * BBUF + v * BPLANE + b * 48 + hf * 16,
                       stbase + (size_t)v * (128 * KG) + b * KG + kofs + g * 16 + hf * 8);
            }
        }
        CP_COMMIT();
    };
    fetch(0); fetch(1);

    float acc[2][2][4];
#pragma unroll
    for (int mt = 0; mt < 2; mt++)
#pragma unroll
        for (int nt = 0; nt < 2; nt++)
#pragma unroll
            for (int q = 0; q < 4; q++) acc[mt][nt][q] = 0.f;

    const int wm = warp >> 3, wn = warp & 7;
    const int wplaneB = 128 * wpitchB;
    const u32 arow = wsm + (u32)((wm * 32 + (lane & 15)) * wpitchB) + (u32)(((lane >> 4) & 1) << 4);
    const u32 brow = (u32)((wn * 16 + (lane & 7) + (((lane >> 4) & 1) << 3)) * 48 + (((lane >> 3) & 1) << 4));

    for (int g = 0; g < NG; g++) {
        asm volatile("cp.async.wait_group 1;" ::: "memory");
        __syncthreads();
        fetch(g + 2);
        u32 abase = arow + (u32)(g * 32);
        u32 a[2][3][4];
#pragma unroll
        for (int mt = 0; mt < 2; mt++) {
            u32 ab = abase + (u32)(mt * 16 * wpitchB);
            ldsm_x4(a[mt][0][0], a[mt][0][1], a[mt][0][2], a[mt][0][3], ab);
            ldsm_x4(a[mt][1][0], a[mt][1][1], a[mt][1][2], a[mt][1][3], ab + wplaneB);
            ldsm_x4(a[mt][2][0], a[mt][2][1], a[mt][2][2], a[mt][2][3], ab + 2 * wplaneB);
        }
        u32 bb = bsm + (g % 3) * BBUF + brow;
        u32 b[3][4];
#pragma unroll
        for (int v = 0; v < 3; v++)
            ldsm_x4(b[v][0], b[v][1], b[v][2], b[v][3], bb + v * BPLANE);
#pragma unroll
        for (int mt = 0; mt < 2; mt++)
#pragma unroll
            for (int nt = 0; nt < 2; nt++) {
                int s = nt * 2;
                u32 bh[2] = { b[0][s], b[0][s + 1] };
                u32 bm[2] = { b[1][s], b[1][s + 1] };
                u32 bl[2] = { b[2][s], b[2][s + 1] };
                mma16816(acc[mt][nt], a[mt][0], bh);   // hh
                mma16816(acc[mt][nt], a[mt][0], bm);   // hm
                mma16816(acc[mt][nt], a[mt][1], bh);   // mh
                mma16816(acc[mt][nt], a[mt][0], bl);   // hl
                mma16816(acc[mt][nt], a[mt][2], bh);   // lh
                mma16816(acc[mt][nt], a[mt][1], bm);   // mm
            }
    }

    const int c0 = wn * 16 + 2 * (lane & 3);
#pragma unroll
    for (int mt = 0; mt < 2; mt++) {
        int r0 = wm * 32 + mt * 16 + (lane >> 2);
#pragma unroll
        for (int nt = 0; nt < 2; nt++) {
            float2 v0; v0.x = acc[mt][nt][0]; v0.y = acc[mt][nt][1];
            float2 v1; v1.x = acc[mt][nt][2]; v1.y = acc[mt][nt][3];
            *(float2*)(spart + r0 * 128 + c0 + nt * 8) = v0;
            *(float2*)(spart + (r0 + 8) * 128 + c0 + nt * 8) = v1;
        }
    }
}

__device__ __forceinline__ void epi_slstm(int layer, float thr, const float* __restrict__ part,
                                          const float* __restrict__ bi, const float* __restrict__ bh) {
    if (threadIdx.x >= 512) return;
    int e = blockIdx.x * 512 + threadIdx.x;
    int h = e >> 7, b = e & 127;
    float sums[4];
#pragma unroll
    for (int gt = 0; gt < 4; gt++) {
        int r = gt * 512 + h;
        const float* pp = part + (r >> 7) * 16384 + (r & 127) * 128 + b;
        float s = 0.f;
#pragma unroll
        for (int sp = 0; sp < NSPLIT; sp++) s += __ldcg(pp + sp * (2048 * 128));
        sums[gt] = s + __ldg(bi + r) + __ldg(bh + r);
    }
    float* syn = (layer == 1) ? g_syn1 : g_syn2;
    float* memr = (layer == 1) ? g_mem1f : g_mem2f;
    float sv = syn[e], mo = memr[e];
    float reset = (mo > thr) ? thr : 0.f;
    float sn = sigf(sums[1]) * sv + sigf(sums[0]) * tanhf(sums[2]);
    float mn = sigf(sums[3]) * tanhf(sn) - reset;
    syn[e] = sn; memr[e] = mn;
    u16 sh, sm, sl;
    split3(mn, sh, sm, sl);
    if (layer == 1) {
        int idx = b * K1P + 64 + h;
        g_St1[0][idx] = sh; g_St1[1][idx] = sm; g_St1[2][idx] = sl;
        g_St2[0][b * K2 + h] = (mn > thr) ? (u16)0x3F80 : (u16)0;
    } else {
        int idx = b * K2 + 512 + h;
        g_St2[0][idx] = sh; g_St2[1][idx] = sm; g_St2[2][idx] = sl;
        g_acc2[e] += mn;
    }
}

__device__ __forceinline__ void lif_phase(int t, float thrL) {
    if (threadIdx.x < 64) {
        int e = blockIdx.x * 64 + threadIdx.x;
        float mo = g_memL[e];
        float xt = g_seq[t * 8192 + e];
        float reset = (mo > thrL) ? thrL : 0.f;
        float mn = 0.9f * mo + xt - reset;
        g_memL[e] = mn;
        g_St1[0][(e & 127) * K1P + (e >> 7)] = (mn > thrL) ? (u16)0x3F80 : (u16)0;
    }
}

__global__ void __launch_bounds__(1024, 1) scan_kernel(
    const float* __restrict__ w_ih1, const float* __restrict__ w_hh1,
    const float* __restrict__ b_ih1, const float* __restrict__ b_hh1,
    const float* __restrict__ w_ih2, const float* __restrict__ w_hh2,
    const float* __restrict__ b_ih2, const float* __restrict__ b_hh2,
    const float* __restrict__ thrL_p, const float* __restrict__ thr1_p,
    const float* __restrict__ thr2_p)
{
    extern __shared__ char smem[];
    const int tid = threadIdx.x;
    const int cta = blockIdx.x;
    const int tile = cta >> 3, split = cta & 7;
    const int warp = tid >> 5, lane = tid & 31;
    const float thrL = __ldg(thrL_p), thr1 = __ldg(thr1_p), thr2 = __ldg(thr2_p);
    const int gid = cta * 1024 + tid;
    u32 base = smem_u32(smem);
    u32 w1sm = base + SM_W1, w2sm = base + SM_W2, bsm = base + SM_B;

    unsigned ph;
    asm volatile("ld.relaxed.gpu.u32 %0, [%1];" : "=r"(ph) : "l"(g_flags + cta));

    // zero recurrent state + planes
    if (gid < 65536) {
        g_mem1f[gid] = 0.f; g_mem2f[gid] = 0.f;
        g_syn1[gid] = 0.f; g_syn2[gid] = 0.f; g_acc2[gid] = 0.f;
    }
    for (int i = gid; i < 3 * BATCH * K1P; i += 131072) (&g_St1[0][0])[i] = 0;
    for (int i = gid; i < 3 * BATCH * K2; i += 131072) (&g_St2[0][0])[i] = 0;

    // split weights into smem planes [gate][k], padded pitch
    {
        u16* p1 = (u16*)(smem + SM_W1);
        for (int i = tid; i < 128 * K1S; i += 1024) {
            int g = i / K1S, kl = i - g * K1S;
            int R = tile * 128 + g;
            int kg = split * K1S + kl;
            float w = 0.f;
            if (kg < 64) w = __ldg(w_ih1 + R * 64 + kg);
            else if (kg < 576) w = __ldg(w_hh1 + R * 512 + kg - 64);
            u16 h, m, l; split3(w, h, m, l);
            int o = g * W1PITCH + kl;
            p1[o] = h; p1[128 * W1PITCH + o] = m; p1[2 * 128 * W1PITCH + o] = l;
        }
        u16* p2 = (u16*)(smem + SM_W2);
        for (int i = tid; i < 128 * K2S; i += 1024) {
            int g = i >> 7, kl = i & 127;
            int R = tile * 128 + g;
            int kg = split * K2S + kl;
            float w = (kg < 512) ? __ldg(w_ih2 + R * 512 + kg) : __ldg(w_hh2 + R * 512 + kg - 512);
            u16 h, m, l; split3(w, h, m, l);
            int o = g * W2PITCH + kl;
            p2[o] = h; p2[128 * W2PITCH + o] = m; p2[2 * 128 * W2PITCH + o] = l;
        }
    }

    if (tid < 64) {  // LIF t=0: mem = x
        int e = cta * 64 + tid;
        float xt = g_seq[e];
        g_memL[e] = xt;
        g_St1[0][(e & 127) * K1P + (e >> 7)] = (xt > thrL) ? (u16)0x3F80 : (u16)0;
    }
    __syncthreads();
    ph++; grid_barrier(ph);

    float* spartA = g_partA + split * 262144 + tile * 16384;
    float* spartB = g_partB + split * 262144 + tile * 16384;

    for (int t = 0; t < T_STEPS; t++) {
        gemm_mma<G1, K1P>(&g_St1[0][0], split * K1S, w1sm, W1PITCH * 2, bsm, spartA, warp, lane);
        ph++; grid_barrier(ph);
        epi_slstm(1, thr1, g_partA, b_ih1, b_hh1);
        if (t + 1 < T_STEPS) lif_phase(t + 1, thrL);
        ph++; grid_barrier(ph);
        gemm_mma<G2, K2>(&g_St2[0][0], split * K2S, w2sm, W2PITCH * 2, bsm, spartB, warp, lane);
        ph++; grid_barrier(ph);
        epi_slstm(2, thr2, g_partB, b_ih2, b_hh2);
    }
}

__global__ void heads_kernel(const float* __restrict__ wg, const float* __restrict__ bg,
                             const float* __restrict__ wd1, const float* __restrict__ bd1,
                             const float* __restrict__ wd2, const float* __restrict__ bd2,
                             const float* __restrict__ thr_dom_p, float* __restrict__ out)
{
    __shared__ float feat[512];
    __shared__ float sd[64];
    int b = blockIdx.x, tid = threadIdx.x;
    const float thr = *thr_dom_p;
#pragma unroll
    for (int j = 0; j < 4; j++)
        feat[tid + j * 128] = g_acc2[(tid + j * 128) * 128 + b] * (1.f / 400.f);
    __syncthreads();
    if (tid < 8) {
        float acc = bg[tid];
        for (int h = 0; h < 512; h++) acc = fmaf(feat[h], wg[tid * 512 + h], acc);
        out[b * 8 + tid] = acc;
    }
    if (tid < 64) {
        float acc = bd1[tid];
        for (int h = 0; h < 512; h++) acc = fmaf(feat[h], wd1[tid * 512 + h], acc);
        sd[tid] = (acc - thr > 0.f) ? 1.f : 0.f;
    }
    __syncthreads();
    if (tid < 10) {
        float acc = bd2[tid];
        for (int k = 0; k < 64; k++) acc = fmaf(sd[k], wd2[tid * 64 + k], acc);
        out[128 * 8 + b * 10 + tid] = acc;
    }
}

extern "C" void kernel_launch(void* const* d_in, const int* in_sizes, int n_in,
                              void* d_out, int out_size) {
    const float* x      = (const float*)d_in[0];
    const float* conv_w = (const float*)d_in[1];
    const float* bn_g   = (const float*)d_in[2];
    const float* bn_b   = (const float*)d_in[3];
    const float* w_ih1  = (const float*)d_in[4];
    const float* w_hh1  = (const float*)d_in[5];
    const float* b_ih1  = (const float*)d_in[6];
    const float* b_hh1  = (const float*)d_in[7];
    const float* w_ih2  = (const float*)d_in[8];
    const float* w_hh2  = (const float*)d_in[9];
    const float* b_ih2  = (const float*)d_in[10];
    const float* b_hh2  = (const float*)d_in[11];
    const float* wg     = (const float*)d_in[12];
    const float* bg     = (const float*)d_in[13];
    const float* wd1    = (const float*)d_in[14];
    const float* bd1    = (const float*)d_in[15];
    const float* wd2    = (const float*)d_in[16];
    const float* bd2    = (const float*)d_in[17];
    const float* thrL   = (const float*)d_in[18];
    const float* thr1   = (const float*)d_in[19];
    const float* thr2   = (const float*)d_in[20];
    const float* thrD   = (const float*)d_in[21];

    cudaFuncSetAttribute(scan_kernel, cudaFuncAttributeMaxDynamicSharedMemorySize, SMEM_TOTAL);
    conv_kernel<<<T_STEPS, 128>>>(x, conv_w);
    stats_kernel<<<OC, 256>>>(bn_g, bn_b);
    norm_kernel<<<(OC * T_STEPS * BATCH + 255) / 256, 256>>>();
    scan_kernel<<<128, 1024, SMEM_TOTAL>>>(w_ih1, w_hh1, b_ih1, b_hh1,
                                           w_ih2, w_hh2, b_ih2, b_hh2, thrL, thr1, thr2);
    heads_kernel<<<128, 128>>>(wg, bg, wd1, bd1, wd2, bd2, thrD, (float*)d_out);
}

// round 16
// speedup vs baseline: 1.0806x; 1.0806x over previous
#include <cuda_runtime.h>
#include <cuda_bf16.h>
#include <math.h>

#define T_STEPS 400
#define BATCH 128
#define HID 512
#define OC 64
#define NSPLIT 8
#define K1P 640
#define K2 1024
#define G1 5
#define G2 8
#define W1PITCH 88
#define W2PITCH 136
#define SM_W1 0
#define SM_W2 67584
#define SM_B  172032
#define SMEM_TOTAL 227328
#define BPLANE 6144
#define BBUF 18432

typedef unsigned long long ull;
typedef unsigned short u16;
typedef unsigned int u32;

__device__ __align__(16) float g_ybuf[OC * T_STEPS * BATCH];
__device__ __align__(16) float g_seq [T_STEPS * OC * BATCH];
__device__ float g_scale[OC];
__device__ float g_shift[OC];
__device__ __align__(16) float g_memL[OC * BATCH];
__device__ __align__(16) float g_mem1f[HID * BATCH];
__device__ __align__(16) float g_mem2f[HID * BATCH];
__device__ __align__(16) float g_syn1[HID * BATCH];
__device__ __align__(16) float g_syn2[HID * BATCH];
__device__ __align__(16) float g_acc2[HID * BATCH];
__device__ __align__(16) float g_partA[NSPLIT * 2048 * BATCH];
__device__ __align__(16) float g_partB[NSPLIT * 2048 * BATCH];
__device__ __align__(16) u16 g_St1[3][BATCH * K1P];
__device__ __align__(16) u16 g_St2[3][BATCH * K2];
__device__ unsigned g_flags[128];
__device__ unsigned g_phase;

__device__ __forceinline__ float sigf(float x) { return 1.f / (1.f + expf(-x)); }
__device__ __forceinline__ u32 smem_u32(const void* p) {
    u32 a; asm("{ .reg .u64 t; cvta.to.shared.u64 t, %1; cvt.u32.u64 %0, t; }" : "=r"(a) : "l"(p));
    return a;
}
__device__ __forceinline__ void cpa16s(u32 dst, const void* src) {
    asm volatile("cp.async.cg.shared.global [%0], [%1], 16;" :: "r"(dst), "l"(src));
}
#define CP_COMMIT() asm volatile("cp.async.commit_group;" ::: "memory")
__device__ __forceinline__ void split3(float x, u16& h, u16& m, u16& l) {
    __nv_bfloat16 bh = __float2bfloat16(x);
    float r = x - __bfloat162float(bh);
    __nv_bfloat16 bm = __float2bfloat16(r);
    __nv_bfloat16 bl = __float2bfloat16(r - __bfloat162float(bm));
    h = *(u16*)&bh; m = *(u16*)&bm; l = *(u16*)&bl;
}
__device__ __forceinline__ void ldsm_x4(u32& r0, u32& r1, u32& r2, u32& r3, u32 addr) {
    asm volatile("ldmatrix.sync.aligned.m8n8.x4.shared.b16 {%0,%1,%2,%3}, [%4];"
        : "=r"(r0), "=r"(r1), "=r"(r2), "=r"(r3) : "r"(addr));
}
__device__ __forceinline__ void mma16816(float* c, const u32* a, const u32* b) {
    asm volatile("mma.sync.aligned.m16n8k16.row.col.f32.bf16.bf16.f32 "
        "{%0,%1,%2,%3},{%4,%5,%6,%7},{%8,%9},{%0,%1,%2,%3};"
        : "+f"(c[0]), "+f"(c[1]), "+f"(c[2]), "+f"(c[3])
        : "r"(a[0]), "r"(a[1]), "r"(a[2]), "r"(a[3]), "r"(b[0]), "r"(b[1]));
}

__device__ __forceinline__ void grid_barrier(unsigned ph) {
    __syncthreads();
    if (threadIdx.x == 0)
        asm volatile("st.release.gpu.u32 [%0], %1;" :: "l"(g_flags + blockIdx.x), "r"(ph) : "memory");
    if (blockIdx.x == 0) {
        if (threadIdx.x < 128) {
            unsigned v;
            do { asm volatile("ld.acquire.gpu.u32 %0, [%1];" : "=r"(v) : "l"(g_flags + threadIdx.x)); }
            while ((int)(v - ph) < 0);
        }
        __syncthreads();
        if (threadIdx.x == 0)
            asm volatile("st.release.gpu.u32 [%0], %1;" :: "l"(&g_phase), "r"(ph) : "memory");
    } else if (threadIdx.x == 0) {
        unsigned v;
        do { asm volatile("ld.acquire.gpu.u32 %0, [%1];" : "=r"(v) : "l"(&g_phase)); }
        while ((int)(v - ph) < 0);
    }
    __syncthreads();
}

__global__ void conv_kernel(const float* __restrict__ x, const float* __restrict__ w) {
    __shared__ float s_w[OC * 70];
    int t = blockIdx.x, b = threadIdx.x;
    for (int i = b; i < OC * 70; i += 128) s_w[i] = w[i];
    float xr[5][14];
#pragma unroll
    for (int k = 0; k < 5; k++) {
        int tt = t + k - 2;
        bool ok = (tt >= 0 && tt < T_STEPS);
#pragma unroll
        for (int c = 0; c < 14; c++) xr[k][c] = ok ? x[(tt * BATCH + b) * 14 + c] : 0.f;
    }
    __syncthreads();
    for (int oc = 0; oc < OC; oc++) {
        float acc = 0.f;
        const float* wr = s_w + oc * 70;
#pragma unroll
        for (int c = 0; c < 14; c++)
#pragma unroll
            for (int k = 0; k < 5; k++) acc = fmaf(xr[k][c], wr[c * 5 + k], acc);
        g_ybuf[oc * (T_STEPS * BATCH) + t * BATCH + b] = acc;
    }
}

__global__ void stats_kernel(const float* __restrict__ bn_g, const float* __restrict__ bn_b) {
    int c = blockIdx.x;
    const float* base = g_ybuf + c * (T_STEPS * BATCH);
    double s = 0.0, sq = 0.0;
    for (int i = threadIdx.x; i < T_STEPS * BATCH; i += 256) {
        float v = base[i]; s += v; sq += (double)v * (double)v;
    }
    __shared__ double rs[256], rq[256];
    rs[threadIdx.x] = s; rq[threadIdx.x] = sq;
    __syncthreads();
    for (int st = 128; st > 0; st >>= 1) {
        if (threadIdx.x < st) { rs[threadIdx.x] += rs[threadIdx.x + st]; rq[threadIdx.x] += rq[threadIdx.x + st]; }
        __syncthreads();
    }
    if (threadIdx.x == 0) {
        double n = (double)(T_STEPS * BATCH);
        double mu = rs[0] / n, var = rq[0] / n - mu * mu;
        float sc = bn_g[c] * (float)(1.0 / sqrt(var + 1e-5));
        g_scale[c] = sc; g_shift[c] = bn_b[c] - (float)mu * sc;
    }
}

__global__ void norm_kernel() {
    int i = blockIdx.x * 256 + threadIdx.x;
    if (i >= OC * T_STEPS * BATCH) return;
    int oc = i / (T_STEPS * BATCH), rem = i % (T_STEPS * BATCH);
    g_seq[(rem / BATCH) * (OC * BATCH) + oc * BATCH + (rem % BATCH)] = g_ybuf[i] * g_scale[oc] + g_shift[oc];
}

// gemm phase. LAYER 1: 5 groups (g0 = spike 8k + 8 zero-pad, g1-4 mem1).
// LAYER 2: 8 groups (g0-3 = spk1 (spike), g4-7 = mem2).
// Spike groups: B has only h-plane (m=l exactly 0) -> 3 cross terms.
// 32 warps, warp tile m32 x n16 (4 x 8 warp grid).
template <int LAYER>
__device__ __forceinline__ void gemm_phase(const u16* st, int split, u32 wsm, u32 bsm,
                                           float* __restrict__ spart, int warp, int lane) {
    constexpr int NG = (LAYER == 1) ? G1 : G2;
    constexpr int KG = (LAYER == 1) ? K1P : K2;
    constexpr int WPB = ((LAYER == 1) ? W1PITCH : W2PITCH) * 2;

    auto fetch = [&](int g) {
        if (g < NG) {
            bool spike = (LAYER == 1) ? (g == 0) : (g < 4);
            int buf = g % 3;
            if (spike) {
                for (int i = threadIdx.x; i < 256; i += 1024) {
                    int b = i >> 1, hf = i & 1;
                    const u16* src;
                    if (LAYER == 1) src = hf ? (st + b * K1P + 576) : (st + b * K1P + 8 * split);
                    else            src = st + b * K2 + 64 * split + g * 16 + hf * 8;
                    cpa16s(bsm + buf * BBUF + b * 48 + hf * 16, src);
                }
            } else {
                for (int i = threadIdx.x; i < 768; i += 1024) {
                    int v = i >> 8, rem = i & 255, b = rem >> 1, hf = rem & 1;
                    const u16* src;
                    if (LAYER == 1)
                        src = st + (size_t)v * (128 * K1P) + b * K1P + 64 + 64 * split + (g - 1) * 16 + hf * 8;
                    else
                        src = st + (size_t)v * (128 * K2) + b * K2 + 512 + 64 * split + (g - 4) * 16 + hf * 8;
                    cpa16s(bsm + buf * BBUF + v * BPLANE + b * 48 + hf * 16, src);
                }
            }
        }
        CP_COMMIT();
    };
    fetch(0); fetch(1);

    float acc[2][2][4];
#pragma unroll
    for (int mt = 0; mt < 2; mt++)
#pragma unroll
        for (int nt = 0; nt < 2; nt++)
#pragma unroll
            for (int q = 0; q < 4; q++) acc[mt][nt][q] = 0.f;

    const int wm = warp >> 3, wn = warp & 7;
    const int wplane = 128 * WPB;
    const u32 arow = wsm + (u32)((wm * 32 + (lane & 15)) * WPB) + (u32)(((lane >> 4) & 1) << 4);
    const u32 brow = (u32)((wn * 16 + (lane & 7) + (((lane >> 4) & 1) << 3)) * 48 + (((lane >> 3) & 1) << 4));

    for (int g = 0; g < NG; g++) {
        asm volatile("cp.async.wait_group 1;" ::: "memory");
        __syncthreads();
        fetch(g + 2);
        bool spike = (LAYER == 1) ? (g == 0) : (g < 4);
        u32 abase = arow + (u32)(g * 32);
        u32 a[2][3][4];
#pragma unroll
        for (int mt = 0; mt < 2; mt++) {
            u32 ab = abase + (u32)(mt * 16 * WPB);
            ldsm_x4(a[mt][0][0], a[mt][0][1], a[mt][0][2], a[mt][0][3], ab);
            ldsm_x4(a[mt][1][0], a[mt][1][1], a[mt][1][2], a[mt][1][3], ab + wplane);
            ldsm_x4(a[mt][2][0], a[mt][2][1], a[mt][2][2], a[mt][2][3], ab + 2 * wplane);
        }
        u32 bb = bsm + (g % 3) * BBUF + brow;
        if (spike) {
            u32 b0[4];
            ldsm_x4(b0[0], b0[1], b0[2], b0[3], bb);
#pragma unroll
            for (int mt = 0; mt < 2; mt++)
#pragma unroll
                for (int nt = 0; nt < 2; nt++) {
                    int s = nt * 2;
                    u32 bh[2] = { b0[s], b0[s + 1] };
                    mma16816(acc[mt][nt], a[mt][0], bh);   // hh
                    mma16816(acc[mt][nt], a[mt][1], bh);   // mh
                    mma16816(acc[mt][nt], a[mt][2], bh);   // lh
                }
        } else {
            u32 b[3][4];
#pragma unroll
            for (int v = 0; v < 3; v++)
                ldsm_x4(b[v][0], b[v][1], b[v][2], b[v][3], bb + v * BPLANE);
#pragma unroll
            for (int mt = 0; mt < 2; mt++)
#pragma unroll
                for (int nt = 0; nt < 2; nt++) {
                    int s = nt * 2;
                    u32 bh[2] = { b[0][s], b[0][s + 1] };
                    u32 bm[2] = { b[1][s], b[1][s + 1] };
                    u32 bl[2] = { b[2][s], b[2][s + 1] };
                    mma16816(acc[mt][nt], a[mt][0], bh);   // hh
                    mma16816(acc[mt][nt], a[mt][0], bm);   // hm
                    mma16816(acc[mt][nt], a[mt][1], bh);   // mh
                    mma16816(acc[mt][nt], a[mt][0], bl);   // hl
                    mma16816(acc[mt][nt], a[mt][2], bh);   // lh
                    mma16816(acc[mt][nt], a[mt][1], bm);   // mm
                }
        }
    }

    const int c0 = wn * 16 + 2 * (lane & 3);
#pragma unroll
    for (int mt = 0; mt < 2; mt++) {
        int r0 = wm * 32 + mt * 16 + (lane >> 2);
#pragma unroll
        for (int nt = 0; nt < 2; nt++) {
            float2 v0; v0.x = acc[mt][nt][0]; v0.y = acc[mt][nt][1];
            float2 v1; v1.x = acc[mt][nt][2]; v1.y = acc[mt][nt][3];
            *(float2*)(spart + r0 * 128 + c0 + nt * 8) = v0;
            *(float2*)(spart + (r0 + 8) * 128 + c0 + nt * 8) = v1;
        }
    }
}

__device__ __forceinline__ void epi_slstm(int layer, float thr, const float* __restrict__ part,
                                          const float* __restrict__ bi, const float* __restrict__ bh) {
    if (threadIdx.x >= 512) return;
    int e = blockIdx.x * 512 + threadIdx.x;
    int h = e >> 7, b = e & 127;
    float sums[4];
#pragma unroll
    for (int gt = 0; gt < 4; gt++) {
        int r = gt * 512 + h;
        const float* pp = part + (r >> 7) * 16384 + (r & 127) * 128 + b;
        float s = 0.f;
#pragma unroll
        for (int sp = 0; sp < NSPLIT; sp++) s += __ldcg(pp + sp * (2048 * 128));
        sums[gt] = s + __ldg(bi + r) + __ldg(bh + r);
    }
    float* syn = (layer == 1) ? g_syn1 : g_syn2;
    float* memr = (layer == 1) ? g_mem1f : g_mem2f;
    float sv = syn[e], mo = memr[e];
    float reset = (mo > thr) ? thr : 0.f;
    float sn = sigf(sums[1]) * sv + sigf(sums[0]) * tanhf(sums[2]);
    float mn = sigf(sums[3]) * tanhf(sn) - reset;
    syn[e] = sn; memr[e] = mn;
    u16 sh, sm, sl;
    split3(mn, sh, sm, sl);
    if (layer == 1) {
        int idx = b * K1P + 64 + h;
        g_St1[0][idx] = sh; g_St1[1][idx] = sm; g_St1[2][idx] = sl;
        g_St2[0][b * K2 + h] = (mn > thr) ? (u16)0x3F80 : (u16)0;
    } else {
        int idx = b * K2 + 512 + h;
        g_St2[0][idx] = sh; g_St2[1][idx] = sm; g_St2[2][idx] = sl;
        g_acc2[e] += mn;
    }
}

__device__ __forceinline__ void lif_phase(int t, float thrL) {
    if (threadIdx.x < 64) {
        int e = blockIdx.x * 64 + threadIdx.x;
        float mo = g_memL[e];
        float xt = g_seq[t * 8192 + e];
        float reset = (mo > thrL) ? thrL : 0.f;
        float mn = 0.9f * mo + xt - reset;
        g_memL[e] = mn;
        g_St1[0][(e & 127) * K1P + (e >> 7)] = (mn > thrL) ? (u16)0x3F80 : (u16)0;
    }
}

__global__ void __launch_bounds__(1024, 1) scan_kernel(
    const float* __restrict__ w_ih1, const float* __restrict__ w_hh1,
    const float* __restrict__ b_ih1, const float* __restrict__ b_hh1,
    const float* __restrict__ w_ih2, const float* __restrict__ w_hh2,
    const float* __restrict__ b_ih2, const float* __restrict__ b_hh2,
    const float* __restrict__ thrL_p, const float* __restrict__ thr1_p,
    const float* __restrict__ thr2_p)
{
    extern __shared__ char smem[];
    const int tid = threadIdx.x;
    const int cta = blockIdx.x;
    const int tile = cta >> 3, split = cta & 7;
    const int warp = tid >> 5, lane = tid & 31;
    const float thrL = __ldg(thrL_p), thr1 = __ldg(thr1_p), thr2 = __ldg(thr2_p);
    const int gid = cta * 1024 + tid;
    u32 base = smem_u32(smem);
    u32 w1sm = base + SM_W1, w2sm = base + SM_W2, bsm = base + SM_B;

    unsigned ph;
    asm volatile("ld.relaxed.gpu.u32 %0, [%1];" : "=r"(ph) : "l"(g_flags + cta));

    // zero recurrent state + planes
    if (gid < 65536) {
        g_mem1f[gid] = 0.f; g_mem2f[gid] = 0.f;
        g_syn1[gid] = 0.f; g_syn2[gid] = 0.f; g_acc2[gid] = 0.f;
    }
    for (int i = gid; i < 3 * BATCH * K1P; i += 131072) (&g_St1[0][0])[i] = 0;
    for (int i = gid; i < 3 * BATCH * K2; i += 131072) (&g_St2[0][0])[i] = 0;

    // split weights into smem planes [gate][k], padded pitch, new k mapping
    {
        u16* p1 = (u16*)(smem + SM_W1);
        for (int i = tid; i < 128 * 80; i += 1024) {
            int g = i / 80, kl = i - g * 80;
            int R = tile * 128 + g;
            float w;
            if (kl < 16) w = (kl < 8) ? __ldg(w_ih1 + R * 64 + 8 * split + kl) : 0.f;
            else         w = __ldg(w_hh1 + R * 512 + 64 * split + (kl - 16));
            u16 h, m, l; split3(w, h, m, l);
            int o = g * W1PITCH + kl;
            p1[o] = h; p1[128 * W1PITCH + o] = m; p1[2 * 128 * W1PITCH + o] = l;
        }
        u16* p2 = (u16*)(smem + SM_W2);
        for (int i = tid; i < 128 * 128; i += 1024) {
            int g = i >> 7, kl = i & 127;
            int R = tile * 128 + g;
            float w = (kl < 64) ? __ldg(w_ih2 + R * 512 + 64 * split + kl)
                                : __ldg(w_hh2 + R * 512 + 64 * split + (kl - 64));
            u16 h, m, l; split3(w, h, m, l);
            int o = g * W2PITCH + kl;
            p2[o] = h; p2[128 * W2PITCH + o] = m; p2[2 * 128 * W2PITCH + o] = l;
        }
    }

    if (tid < 64) {  // LIF t=0: mem = x
        int e = cta * 64 + tid;
        float xt = g_seq[e];
        g_memL[e] = xt;
        g_St1[0][(e & 127) * K1P + (e >> 7)] = (xt > thrL) ? (u16)0x3F80 : (u16)0;
    }
    __syncthreads();
    ph++; grid_barrier(ph);

    float* spartA = g_partA + split * 262144 + tile * 16384;
    float* spartB = g_partB + split * 262144 + tile * 16384;

    // 2 barriers per step: gemm1 | bar | epi2(t-1)+epi1+lif | bar | gemm2 -> loop
    for (int t = 0; t < T_STEPS; t++) {
        gemm_phase<1>(&g_St1[0][0], split, w1sm, bsm, spartA, warp, lane);
        ph++; grid_barrier(ph);
        if (t > 0) epi_slstm(2, thr2, g_partB, b_ih2, b_hh2);
        epi_slstm(1, thr1, g_partA, b_ih1, b_hh1);
        if (t + 1 < T_STEPS) lif_phase(t + 1, thrL);
        ph++; grid_barrier(ph);
        gemm_phase<2>(&g_St2[0][0], split, w2sm, bsm, spartB, warp, lane);
    }
    ph++; grid_barrier(ph);
    epi_slstm(2, thr2, g_partB, b_ih2, b_hh2);
}

__global__ void heads_kernel(const float* __restrict__ wg, const float* __restrict__ bg,
                             const float* __restrict__ wd1, const float* __restrict__ bd1,
                             const float* __restrict__ wd2, const float* __restrict__ bd2,
                             const float* __restrict__ thr_dom_p, float* __restrict__ out)
{
    __shared__ float feat[512];
    __shared__ float sd[64];
    int b = blockIdx.x, tid = threadIdx.x;
    const float thr = *thr_dom_p;
#pragma unroll
    for (int j = 0; j < 4; j++)
        feat[tid + j * 128] = g_acc2[(tid + j * 128) * 128 + b] * (1.f / 400.f);
    __syncthreads();
    if (tid < 8) {
        float acc = bg[tid];
        for (int h = 0; h < 512; h++) acc = fmaf(feat[h], wg[tid * 512 + h], acc);
        out[b * 8 + tid] = acc;
    }
    if (tid < 64) {
        float acc = bd1[tid];
        for (int h = 0; h < 512; h++) acc = fmaf(feat[h], wd1[tid * 512 + h], acc);
        sd[tid] = (acc - thr > 0.f) ? 1.f : 0.f;
    }
    __syncthreads();
    if (tid < 10) {
        float acc = bd2[tid];
        for (int k = 0; k < 64; k++) acc = fmaf(sd[k], wd2[tid * 64 + k], acc);
        out[128 * 8 + b * 10 + tid] = acc;
    }
}

extern "C" void kernel_launch(void* const* d_in, const int* in_sizes, int n_in,
                              void* d_out, int out_size) {
    const float* x      = (const float*)d_in[0];
    const float* conv_w = (const float*)d_in[1];
    const float* bn_g   = (const float*)d_in[2];
    const float* bn_b   = (const float*)d_in[3];
    const float* w_ih1  = (const float*)d_in[4];
    const float* w_hh1  = (const float*)d_in[5];
    const float* b_ih1  = (const float*)d_in[6];
    const float* b_hh1  = (const float*)d_in[7];
    const float* w_ih2  = (const float*)d_in[8];
    const float* w_hh2  = (const float*)d_in[9];
    const float* b_ih2  = (const float*)d_in[10];
    const float* b_hh2  = (const float*)d_in[11];
    const float* wg     = (const float*)d_in[12];
    const float* bg     = (const float*)d_in[13];
    const float* wd1    = (const float*)d_in[14];
    const float* bd1    = (const float*)d_in[15];
    const float* wd2    = (const float*)d_in[16];
    const float* bd2    = (const float*)d_in[17];
    const float* thrL   = (const float*)d_in[18];
    const float* thr1   = (const float*)d_in[19];
    const float* thr2   = (const float*)d_in[20];
    const float* thrD   = (const float*)d_in[21];

    cudaFuncSetAttribute(scan_kernel, cudaFuncAttributeMaxDynamicSharedMemorySize, SMEM_TOTAL);
    conv_kernel<<<T_STEPS, 128>>>(x, conv_w);
    stats_kernel<<<OC, 256>>>(bn_g, bn_b);
    norm_kernel<<<(OC * T_STEPS * BATCH + 255) / 256, 256>>>();
    scan_kernel<<<128, 1024, SMEM_TOTAL>>>(w_ih1, w_hh1, b_ih1, b_hh1,
                                           w_ih2, w_hh2, b_ih2, b_hh2, thrL, thr1, thr2);
    heads_kernel<<<128, 128>>>(wg, bg, wd1, bd1, wd2, bd2, thrD, (float*)d_out);
}